// round 3
// baseline (speedup 1.0000x reference)
#include <cuda_runtime.h>

#define NN 10000
#define EE 40000
#define FIN 30
#define FE 11
#define EMB 64
#define BB 128
#define HC 17           // 16 hidden channels + 1 folded-bias channel
#define ZC (HC * EMB)   // 1088

// ---------------- device scratch (static globals — no allocation) ----------------
__device__ float g_h0[EE * HC];      // layer-0 edge MLP output (+1 channel)
__device__ float g_h1[EE * HC];      // layer-1/2 edge MLP output (shared weights)
__device__ float g_Wr0[FIN * ZC];    // rearranged w2 for layer 0: [in, 17*64]
__device__ float g_Wr1[EMB * ZC];    // rearranged w2 for layers 1-2
__device__ float g_z[NN * ZC];       // per-node factorized tensor [N, 17*64]
__device__ float g_bufA[NN * EMB];
__device__ float g_bufB[NN * EMB];
__device__ float g_agg[NN * EMB];
__device__ float g_pool[BB * EMB];
__device__ float g_v[EMB + 1];       // collapsed head vector + scalar

// ---------------- kernels ----------------

__global__ void zero_kernel(float* p, int n) {
    for (int i = blockIdx.x * blockDim.x + threadIdx.x; i < n; i += gridDim.x * blockDim.x)
        p[i] = 0.f;
}

// h = relu(edge_attr @ w1 + b1), with trailing 1.0 channel. Two weight sets at once.
__global__ void edge_mlp_kernel(const float* __restrict__ ea,
                                const float* __restrict__ w1a, const float* __restrict__ b1a,
                                const float* __restrict__ w1b, const float* __restrict__ b1b) {
    __shared__ float swa[FE * 16], swb[FE * 16], sba[16], sbb[16];
    int tid = threadIdx.x;
    for (int t = tid; t < FE * 16; t += blockDim.x) { swa[t] = w1a[t]; swb[t] = w1b[t]; }
    if (tid < 16) { sba[tid] = b1a[tid]; sbb[tid] = b1b[tid]; }
    __syncthreads();
    int e = blockIdx.x * blockDim.x + tid;
    if (e >= EE) return;
    float a[FE];
#pragma unroll
    for (int i = 0; i < FE; i++) a[i] = ea[e * FE + i];
#pragma unroll
    for (int j = 0; j < 16; j++) {
        float s = sba[j], s2 = sbb[j];
#pragma unroll
        for (int i = 0; i < FE; i++) { s += a[i] * swa[i * 16 + j]; s2 += a[i] * swb[i * 16 + j]; }
        g_h0[e * HC + j] = fmaxf(s, 0.f);
        g_h1[e * HC + j] = fmaxf(s2, 0.f);
    }
    g_h0[e * HC + 16] = 1.f;
    g_h1[e * HC + 16] = 1.f;
}

// Wr[i, k*64+o] = w2[k, i*64+o] for k<16 ; Wr[i, 16*64+o] = b2[i*64+o]
__global__ void build_wr_kernel(const float* __restrict__ w2, const float* __restrict__ b2,
                                float* __restrict__ Wr, int in_dim) {
    int idx = blockIdx.x * blockDim.x + threadIdx.x;
    int total = in_dim * ZC;
    if (idx >= total) return;
    int i = idx / ZC;
    int r = idx - i * ZC;
    int k = r >> 6;
    int o = r & 63;
    Wr[idx] = (k < 16) ? w2[k * (in_dim * EMB) + i * EMB + o] : b2[i * EMB + o];
}

// C[M x 1088] = A[M x K] @ B[K x 1088].  64x64 tile, 256 threads, 4x4 microtile.
#define GK 32
__global__ __launch_bounds__(256) void gemm_kernel(const float* __restrict__ A,
                                                   const float* __restrict__ B,
                                                   float* __restrict__ C, int M, int K) {
    __shared__ float As[GK][64 + 1];
    __shared__ float Bs[GK][64 + 1];
    int tid = threadIdx.x;
    int tx = tid & 15, ty = tid >> 4;
    int m0 = blockIdx.y * 64, n0 = blockIdx.x * 64;
    float acc[4][4] = {};
    for (int kb = 0; kb < K; kb += GK) {
        for (int t = tid; t < 64 * GK; t += 256) {
            int m = t / GK, k = t - m * GK;
            int gm = m0 + m, gk = kb + k;
            As[k][m] = (gm < M && gk < K) ? A[(size_t)gm * K + gk] : 0.f;
        }
        for (int t = tid; t < GK * 64; t += 256) {
            int k = t >> 6, n = t & 63;
            int gk = kb + k;
            Bs[k][n] = (gk < K) ? B[(size_t)gk * ZC + n0 + n] : 0.f;
        }
        __syncthreads();
#pragma unroll
        for (int k = 0; k < GK; k++) {
            float ra[4], rb[4];
#pragma unroll
            for (int i = 0; i < 4; i++) ra[i] = As[k][ty * 4 + i];
#pragma unroll
            for (int j = 0; j < 4; j++) rb[j] = Bs[k][tx * 4 + j];
#pragma unroll
            for (int i = 0; i < 4; i++)
#pragma unroll
                for (int j = 0; j < 4; j++) acc[i][j] += ra[i] * rb[j];
        }
        __syncthreads();
    }
#pragma unroll
    for (int i = 0; i < 4; i++) {
        int gm = m0 + ty * 4 + i;
        if (gm < M)
#pragma unroll
            for (int j = 0; j < 4; j++) C[(size_t)gm * ZC + n0 + tx * 4 + j] = acc[i][j];
    }
}

// Per edge: msg[o] = sum_k h'[k] * z[src][k*64+o]; atomicAdd into agg[dst].
__global__ __launch_bounds__(256) void edge_agg_kernel(const int* __restrict__ ei,
                                                       const float* __restrict__ h,
                                                       const float* __restrict__ z,
                                                       float* __restrict__ agg) {
    int e = blockIdx.x * 8 + (threadIdx.x >> 5);
    if (e >= EE) return;
    int lane = threadIdx.x & 31;
    int src = ei[e];
    int dst = ei[EE + e];
    const float* zr = z + (size_t)src * ZC;
    float hv = (lane < HC) ? h[e * HC + lane] : 0.f;
    float m0 = 0.f, m1 = 0.f;
#pragma unroll
    for (int k = 0; k < HC; k++) {
        float hk = __shfl_sync(0xFFFFFFFFu, hv, k);
        m0 += hk * zr[k * 64 + lane];
        m1 += hk * zr[k * 64 + 32 + lane];
    }
    atomicAdd(&agg[dst * EMB + lane], m0);
    atomicAdd(&agg[dst * EMB + 32 + lane], m1);
}

// out = relu(agg + xin @ root + bias).  256 threads = 4 nodes x 64 outputs.
__global__ __launch_bounds__(256) void root_relu_kernel(const float* __restrict__ agg,
                                                        const float* __restrict__ xin,
                                                        const float* __restrict__ root,
                                                        const float* __restrict__ bias,
                                                        float* __restrict__ out, int in_dim) {
    __shared__ float sroot[EMB * EMB];
    __shared__ float sbias[EMB];
    int tid = threadIdx.x;
    for (int t = tid; t < in_dim * EMB; t += 256) sroot[t] = root[t];
    if (tid < EMB) sbias[tid] = bias[tid];
    __syncthreads();
    int node = blockIdx.x * 4 + (tid >> 6);
    int o = tid & 63;
    if (node >= NN) return;
    float s = agg[node * EMB + o] + sbias[o];
    const float* xr = xin + (size_t)node * in_dim;
    for (int i = 0; i < in_dim; i++) s += xr[i] * sroot[i * EMB + o];
    out[node * EMB + o] = fmaxf(s, 0.f);
}

// segment_max over sorted batch assignment; binary search for graph boundaries.
__global__ void pool_kernel(const float* __restrict__ h, const int* __restrict__ batch) {
    int b = blockIdx.x, o = threadIdx.x;
    __shared__ int sb[2];
    if (o < 2) {
        int target = b + o, lo = 0, hi = NN;
        while (lo < hi) { int mid = (lo + hi) >> 1; if (batch[mid] < target) lo = mid + 1; else hi = mid; }
        sb[o] = lo;
    }
    __syncthreads();
    float m = -3.402823466e38f;
    for (int n = sb[0]; n < sb[1]; n++) m = fmaxf(m, h[(size_t)n * EMB + o]);
    g_pool[b * EMB + o] = m;
}

// v = lin0_w @ lin1_w ; c = lin0_b . lin1_w + lin1_b
__global__ void head_v_kernel(const float* __restrict__ l0w, const float* __restrict__ l0b,
                              const float* __restrict__ l1w, const float* __restrict__ l1b) {
    int i = threadIdx.x;
    float s = 0.f;
    for (int j = 0; j < EMB; j++) s += l0w[i * EMB + j] * l1w[j];
    g_v[i] = s;
    if (i == 0) {
        float c = l1b[0];
        for (int j = 0; j < EMB; j++) c += l0b[j] * l1w[j];
        g_v[EMB] = c;
    }
}

__global__ void head_out_kernel(float* __restrict__ out) {
    int b = blockIdx.x, t = threadIdx.x;
    __shared__ float red[EMB];
    red[t] = g_pool[b * EMB + t] * g_v[t];
    __syncthreads();
    for (int s = 32; s > 0; s >>= 1) {
        if (t < s) red[t] += red[t + s];
        __syncthreads();
    }
    if (t == 0) out[b] = red[0] + g_v[EMB];
}

// ---------------- launch ----------------
extern "C" void kernel_launch(void* const* d_in, const int* in_sizes, int n_in,
                              void* d_out, int out_size) {
    const float* x     = (const float*)d_in[0];
    const float* ea    = (const float*)d_in[1];
    const int*   ei    = (const int*)d_in[2];
    const int*   batch = (const int*)d_in[3];
    const float* ew0_1 = (const float*)d_in[4];
    const float* eb0_1 = (const float*)d_in[5];
    const float* ew0_2 = (const float*)d_in[6];
    const float* eb0_2 = (const float*)d_in[7];
    const float* ew1_1 = (const float*)d_in[8];
    const float* eb1_1 = (const float*)d_in[9];
    const float* ew1_2 = (const float*)d_in[10];
    const float* eb1_2 = (const float*)d_in[11];
    const float* root0 = (const float*)d_in[12];
    const float* bias0 = (const float*)d_in[13];
    const float* root1 = (const float*)d_in[14];
    const float* bias1 = (const float*)d_in[15];
    const float* root2 = (const float*)d_in[16];
    const float* bias2 = (const float*)d_in[17];
    const float* l0w   = (const float*)d_in[18];
    const float* l0b   = (const float*)d_in[19];
    const float* l1w   = (const float*)d_in[20];
    const float* l1b   = (const float*)d_in[21];
    float* out = (float*)d_out;

    float *h0p, *h1p, *Wr0p, *Wr1p, *zp, *bufAp, *bufBp, *aggp;
    cudaGetSymbolAddress((void**)&h0p,   g_h0);
    cudaGetSymbolAddress((void**)&h1p,   g_h1);
    cudaGetSymbolAddress((void**)&Wr0p,  g_Wr0);
    cudaGetSymbolAddress((void**)&Wr1p,  g_Wr1);
    cudaGetSymbolAddress((void**)&zp,    g_z);
    cudaGetSymbolAddress((void**)&bufAp, g_bufA);
    cudaGetSymbolAddress((void**)&bufBp, g_bufB);
    cudaGetSymbolAddress((void**)&aggp,  g_agg);

    dim3 gemm_grid(ZC / 64, (NN + 63) / 64);

    edge_mlp_kernel<<<(EE + 255) / 256, 256>>>(ea, ew0_1, eb0_1, ew1_1, eb1_1);
    build_wr_kernel<<<(FIN * ZC + 255) / 256, 256>>>(ew0_2, eb0_2, Wr0p, FIN);
    build_wr_kernel<<<(EMB * ZC + 255) / 256, 256>>>(ew1_2, eb1_2, Wr1p, EMB);

    // layer 0
    gemm_kernel<<<gemm_grid, 256>>>(x, Wr0p, zp, NN, FIN);
    zero_kernel<<<256, 256>>>(aggp, NN * EMB);
    edge_agg_kernel<<<(EE + 7) / 8, 256>>>(ei, h0p, zp, aggp);
    root_relu_kernel<<<(NN + 3) / 4, 256>>>(aggp, x, root0, bias0, bufAp, FIN);

    // layer 1
    gemm_kernel<<<gemm_grid, 256>>>(bufAp, Wr1p, zp, NN, EMB);
    zero_kernel<<<256, 256>>>(aggp, NN * EMB);
    edge_agg_kernel<<<(EE + 7) / 8, 256>>>(ei, h1p, zp, aggp);
    root_relu_kernel<<<(NN + 3) / 4, 256>>>(aggp, bufAp, root1, bias1, bufBp, EMB);

    // layer 2 (shared edge-MLP weights -> reuse Wr1 and h1)
    gemm_kernel<<<gemm_grid, 256>>>(bufBp, Wr1p, zp, NN, EMB);
    zero_kernel<<<256, 256>>>(aggp, NN * EMB);
    edge_agg_kernel<<<(EE + 7) / 8, 256>>>(ei, h1p, zp, aggp);
    root_relu_kernel<<<(NN + 3) / 4, 256>>>(aggp, bufBp, root2, bias2, bufAp, EMB);

    // pool + head
    pool_kernel<<<BB, EMB>>>(bufAp, batch);
    head_v_kernel<<<1, EMB>>>(l0w, l0b, l1w, l1b);
    head_out_kernel<<<BB, EMB>>>(out);
}

// round 4
// speedup vs baseline: 1.4229x; 1.4229x over previous
#include <cuda_runtime.h>
#include <cfloat>

#define NN 10000
#define EE 40000
#define FIN 30
#define FE 11
#define EMB 64
#define BB 128
#define HC 17            // 16 hidden channels + 1 folded-bias channel
#define ZC (HC * EMB)    // 1088
#define NB (ZC + EMB)    // 1152 = B matrix width (z cols + root cols)

// ---------------- device scratch (static globals — no allocation) ----------------
__device__ float g_h0[EE * HC];        // layer-0 edge MLP output (+1 channel)
__device__ float g_h1[EE * HC];        // layer-1/2 edge MLP output (shared weights)
__device__ float g_Wr0[FIN * NB];      // [Wr | root0] for layer 0
__device__ float g_Wr1a[EMB * NB];     // [Wr1 | root1]
__device__ float g_Wr1b[EMB * NB];     // [Wr1 | root2]
__device__ float g_z[NN * ZC];         // per-node factorized tensor [N, 17*64]
__device__ float g_P0[NN * EMB];       // preactivation ping
__device__ float g_P1[NN * EMB];       // preactivation pong
__device__ float g_v[EMB + 1];         // collapsed head vector + scalar

// ---------------- kernels ----------------

// h = relu(edge_attr @ w1 + b1), with trailing 1.0 channel. Two weight sets at once.
__global__ void edge_mlp_kernel(const float* __restrict__ ea,
                                const float* __restrict__ w1a, const float* __restrict__ b1a,
                                const float* __restrict__ w1b, const float* __restrict__ b1b) {
    __shared__ float swa[FE * 16], swb[FE * 16], sba[16], sbb[16];
    int tid = threadIdx.x;
    for (int t = tid; t < FE * 16; t += blockDim.x) { swa[t] = w1a[t]; swb[t] = w1b[t]; }
    if (tid < 16) { sba[tid] = b1a[tid]; sbb[tid] = b1b[tid]; }
    __syncthreads();
    int e = blockIdx.x * blockDim.x + tid;
    if (e >= EE) return;
    float a[FE];
#pragma unroll
    for (int i = 0; i < FE; i++) a[i] = ea[e * FE + i];
#pragma unroll
    for (int j = 0; j < 16; j++) {
        float s = sba[j], s2 = sbb[j];
#pragma unroll
        for (int i = 0; i < FE; i++) { s += a[i] * swa[i * 16 + j]; s2 += a[i] * swb[i * 16 + j]; }
        g_h0[e * HC + j] = fmaxf(s, 0.f);
        g_h1[e * HC + j] = fmaxf(s2, 0.f);
    }
    g_h0[e * HC + 16] = 1.f;
    g_h1[e * HC + 16] = 1.f;
}

// Build the three extended weight matrices in one launch.
// Wr[i, k*64+o] = w2[k, i*64+o] (k<16); Wr[i,16*64+o] = b2[i*64+o]; Wr[i,1088+o] = root[i*64+o]
__global__ void build_weights_kernel(const float* __restrict__ w2_0, const float* __restrict__ b2_0,
                                     const float* __restrict__ root0,
                                     const float* __restrict__ w2_1, const float* __restrict__ b2_1,
                                     const float* __restrict__ root1, const float* __restrict__ root2) {
    int idx = blockIdx.x * blockDim.x + threadIdx.x;
    if (idx < EMB * NB) {
        int i = idx / NB, r = idx - i * NB;
        if (r < ZC) {
            int k = r >> 6, o = r & 63;
            float vz = (k < 16) ? w2_1[k * (EMB * EMB) + i * EMB + o] : b2_1[i * EMB + o];
            g_Wr1a[idx] = vz; g_Wr1b[idx] = vz;
        } else {
            int o = r - ZC;
            g_Wr1a[idx] = root1[i * EMB + o];
            g_Wr1b[idx] = root2[i * EMB + o];
        }
    }
    if (idx < FIN * NB) {
        int i = idx / NB, r = idx - i * NB;
        if (r < ZC) {
            int k = r >> 6, o = r & 63;
            g_Wr0[idx] = (k < 16) ? w2_0[k * (FIN * EMB) + i * EMB + o] : b2_0[i * EMB + o];
        } else {
            g_Wr0[idx] = root0[i * EMB + (r - ZC)];
        }
    }
}

// C[M x 1152] = act(A[M x K]) @ B[K x 1152].
// Cols [0,1088) -> z buffer.  Cols [1088,1152) -> agg init (val + bias).
// 128x64 tile, 256 threads, 8x4 microtile, float4 smem traffic.
#define BM 128
#define BN 64
#define BK 32
__global__ __launch_bounds__(256) void gemm_kernel(const float* __restrict__ A,
                                                   const float* __restrict__ B,
                                                   float* __restrict__ z,
                                                   float* __restrict__ agg,
                                                   const float* __restrict__ bias,
                                                   int M, int K, int relu_a) {
    __shared__ float As[BK][BM + 4];   // +4 keeps float4 alignment, breaks k-stride conflicts
    __shared__ float Bs[BK][BN + 4];
    int tid = threadIdx.x;
    int tx = tid & 15, ty = tid >> 4;
    int m0 = blockIdx.y * BM;
    int n0 = blockIdx.x * BN;
    float acc[8][4] = {};

    for (int kb = 0; kb < K; kb += BK) {
        if ((K & 3) == 0) {
            // vectorized A load: float4 along k, scatter into k-major As
            for (int t = tid; t < BM * (BK / 4); t += 256) {
                int m = t >> 3;
                int k4 = (t & 7) << 2;
                int gm = m0 + m, gk = kb + k4;
                float4 v = make_float4(0.f, 0.f, 0.f, 0.f);
                if (gm < M && gk < K) v = *(const float4*)&A[(size_t)gm * K + gk];
                if (relu_a) {
                    v.x = fmaxf(v.x, 0.f); v.y = fmaxf(v.y, 0.f);
                    v.z = fmaxf(v.z, 0.f); v.w = fmaxf(v.w, 0.f);
                }
                As[k4][m] = v.x; As[k4 + 1][m] = v.y; As[k4 + 2][m] = v.z; As[k4 + 3][m] = v.w;
            }
        } else {
            for (int t = tid; t < BM * BK; t += 256) {
                int m = t >> 5, k = t & (BK - 1);
                int gm = m0 + m, gk = kb + k;
                float v = (gm < M && gk < K) ? A[(size_t)gm * K + gk] : 0.f;
                if (relu_a) v = fmaxf(v, 0.f);
                As[k][m] = v;
            }
        }
        for (int t = tid; t < BK * (BN / 4); t += 256) {
            int k = t >> 4;
            int n4 = (t & 15) << 2;
            int gk = kb + k;
            float4 v = make_float4(0.f, 0.f, 0.f, 0.f);
            if (gk < K) v = *(const float4*)&B[(size_t)gk * NB + n0 + n4];
            *(float4*)&Bs[k][n4] = v;
        }
        __syncthreads();
#pragma unroll
        for (int k = 0; k < BK; k++) {
            float4 a0 = *(float4*)&As[k][ty * 8];
            float4 a1 = *(float4*)&As[k][ty * 8 + 4];
            float4 b = *(float4*)&Bs[k][tx * 4];
            float ra[8] = {a0.x, a0.y, a0.z, a0.w, a1.x, a1.y, a1.z, a1.w};
            float rb[4] = {b.x, b.y, b.z, b.w};
#pragma unroll
            for (int i = 0; i < 8; i++)
#pragma unroll
                for (int j = 0; j < 4; j++) acc[i][j] += ra[i] * rb[j];
        }
        __syncthreads();
    }

    if (n0 < ZC) {
#pragma unroll
        for (int i = 0; i < 8; i++) {
            int gm = m0 + ty * 8 + i;
            if (gm < M) {
                float4 v = make_float4(acc[i][0], acc[i][1], acc[i][2], acc[i][3]);
                *(float4*)&z[(size_t)gm * ZC + n0 + tx * 4] = v;
            }
        }
    } else {
        float4 bb = *(const float4*)&bias[tx * 4];
#pragma unroll
        for (int i = 0; i < 8; i++) {
            int gm = m0 + ty * 8 + i;
            if (gm < M) {
                float4 v = make_float4(acc[i][0] + bb.x, acc[i][1] + bb.y,
                                       acc[i][2] + bb.z, acc[i][3] + bb.w);
                *(float4*)&agg[(size_t)gm * EMB + tx * 4] = v;
            }
        }
    }
}

// Per edge: msg[o] = sum_k h'[k] * z[src][k*64+o]; atomicAdd into agg[dst].
__global__ __launch_bounds__(256) void edge_agg_kernel(const int* __restrict__ ei,
                                                       const float* __restrict__ h,
                                                       const float* __restrict__ z,
                                                       float* __restrict__ agg) {
    int e = blockIdx.x * 8 + (threadIdx.x >> 5);
    if (e >= EE) return;
    int lane = threadIdx.x & 31;
    int src = ei[e];
    int dst = ei[EE + e];
    const float* zr = z + (size_t)src * ZC;
    float hv = (lane < HC) ? h[e * HC + lane] : 0.f;
    float m0 = 0.f, m1 = 0.f;
#pragma unroll
    for (int k = 0; k < HC; k++) {
        float hk = __shfl_sync(0xFFFFFFFFu, hv, k);
        m0 += hk * zr[k * 64 + lane];
        m1 += hk * zr[k * 64 + 32 + lane];
    }
    atomicAdd(&agg[dst * EMB + lane], m0);
    atomicAdd(&agg[dst * EMB + 32 + lane], m1);
}

// v = lin0_w @ lin1_w ; c = lin0_b . lin1_w + lin1_b
__global__ void head_v_kernel(const float* __restrict__ l0w, const float* __restrict__ l0b,
                              const float* __restrict__ l1w, const float* __restrict__ l1b) {
    int i = threadIdx.x;
    float s = 0.f;
    for (int j = 0; j < EMB; j++) s += l0w[i * EMB + j] * l1w[j];
    g_v[i] = s;
    if (i == 0) {
        float c = l1b[0];
        for (int j = 0; j < EMB; j++) c += l0b[j] * l1w[j];
        g_v[EMB] = c;
    }
}

// Fused: segment_max(relu(h)) over sorted batch, dot with head vector.
__global__ __launch_bounds__(256) void pool_head_kernel(const float* __restrict__ h,
                                                        const int* __restrict__ batch,
                                                        float* __restrict__ out) {
    int b = blockIdx.x, t = threadIdx.x;
    __shared__ int sb[2];
    __shared__ float sred[256];
    if (t < 2) {
        int target = b + t, lo = 0, hi = NN;
        while (lo < hi) { int mid = (lo + hi) >> 1; if (batch[mid] < target) lo = mid + 1; else hi = mid; }
        sb[t] = lo;
    }
    __syncthreads();
    int o = t & 63, c = t >> 6;
    float m = -FLT_MAX;
    for (int n = sb[0] + c; n < sb[1]; n += 4) m = fmaxf(m, h[(size_t)n * EMB + o]);
    sred[t] = m;
    __syncthreads();
    if (t < 64) {
        float mm = fmaxf(fmaxf(sred[t], sred[t + 64]), fmaxf(sred[t + 128], sred[t + 192]));
        mm = fmaxf(mm, 0.f);   // relu commutes with max; segments are nonempty
        sred[t] = mm * g_v[t];
    }
    __syncthreads();
    for (int s = 32; s > 0; s >>= 1) {
        if (t < s) sred[t] += sred[t + s];
        __syncthreads();
    }
    if (t == 0) out[b] = sred[0] + g_v[EMB];
}

// ---------------- launch ----------------
extern "C" void kernel_launch(void* const* d_in, const int* in_sizes, int n_in,
                              void* d_out, int out_size) {
    const float* x     = (const float*)d_in[0];
    const float* ea    = (const float*)d_in[1];
    const int*   ei    = (const int*)d_in[2];
    const int*   batch = (const int*)d_in[3];
    const float* ew0_1 = (const float*)d_in[4];
    const float* eb0_1 = (const float*)d_in[5];
    const float* ew0_2 = (const float*)d_in[6];
    const float* eb0_2 = (const float*)d_in[7];
    const float* ew1_1 = (const float*)d_in[8];
    const float* eb1_1 = (const float*)d_in[9];
    const float* ew1_2 = (const float*)d_in[10];
    const float* eb1_2 = (const float*)d_in[11];
    const float* root0 = (const float*)d_in[12];
    const float* bias0 = (const float*)d_in[13];
    const float* root1 = (const float*)d_in[14];
    const float* bias1 = (const float*)d_in[15];
    const float* root2 = (const float*)d_in[16];
    const float* bias2 = (const float*)d_in[17];
    const float* l0w   = (const float*)d_in[18];
    const float* l0b   = (const float*)d_in[19];
    const float* l1w   = (const float*)d_in[20];
    const float* l1b   = (const float*)d_in[21];
    float* out = (float*)d_out;

    float *h0p, *h1p, *Wr0p, *Wr1ap, *Wr1bp, *zp, *P0p, *P1p;
    cudaGetSymbolAddress((void**)&h0p,   g_h0);
    cudaGetSymbolAddress((void**)&h1p,   g_h1);
    cudaGetSymbolAddress((void**)&Wr0p,  g_Wr0);
    cudaGetSymbolAddress((void**)&Wr1ap, g_Wr1a);
    cudaGetSymbolAddress((void**)&Wr1bp, g_Wr1b);
    cudaGetSymbolAddress((void**)&zp,    g_z);
    cudaGetSymbolAddress((void**)&P0p,   g_P0);
    cudaGetSymbolAddress((void**)&P1p,   g_P1);

    dim3 gemm_grid(NB / BN, (NN + BM - 1) / BM);   // 18 x 79

    edge_mlp_kernel<<<(EE + 255) / 256, 256>>>(ea, ew0_1, eb0_1, ew1_1, eb1_1);
    build_weights_kernel<<<(EMB * NB + 255) / 256, 256>>>(ew0_2, eb0_2, root0,
                                                          ew1_2, eb1_2, root1, root2);

    // layer 0: P0 = x@root0 + bias0 (gemm epilogue) + scatter(h0, z)
    gemm_kernel<<<gemm_grid, 256>>>(x, Wr0p, zp, P0p, bias0, NN, FIN, 0);
    edge_agg_kernel<<<(EE + 7) / 8, 256>>>(ei, h0p, zp, P0p);

    // layer 1: A = relu(P0)
    gemm_kernel<<<gemm_grid, 256>>>(P0p, Wr1ap, zp, P1p, bias1, NN, EMB, 1);
    edge_agg_kernel<<<(EE + 7) / 8, 256>>>(ei, h1p, zp, P1p);

    // layer 2: A = relu(P1), agg init back into P0
    gemm_kernel<<<gemm_grid, 256>>>(P1p, Wr1bp, zp, P0p, bias2, NN, EMB, 1);
    edge_agg_kernel<<<(EE + 7) / 8, 256>>>(ei, h1p, zp, P0p);

    // head
    head_v_kernel<<<1, EMB>>>(l0w, l0b, l1w, l1b);
    pool_head_kernel<<<BB, 256>>>(P0p, batch, out);
}

// round 7
// speedup vs baseline: 1.4527x; 1.0209x over previous
#include <cuda_runtime.h>
#include <cfloat>

#define NN 10000
#define EE 40000
#define FIN 30
#define FE 11
#define EMB 64
#define BB 128
#define HC 17            // 16 hidden channels + 1 folded-bias channel
#define ZC (HC * EMB)    // 1088
#define NB (ZC + EMB)    // 1152 = B matrix width (z cols + root cols)

// ---------------- device scratch (static globals — no allocation) ----------------
__device__ float g_h0[EE * HC];        // layer-0 edge MLP output (+1 channel)
__device__ float g_h1[EE * HC];        // layer-1/2 edge MLP output (shared weights)
__device__ float g_Wr0[FIN * NB];      // [Wr | root0] for layer 0
__device__ float g_Wr1a[EMB * NB];     // [Wr1 | root1]
__device__ float g_Wr1b[EMB * NB];     // [Wr1 | root2]
__device__ float g_z[NN * ZC];         // per-node factorized tensor [N, 17*64]
__device__ float g_P0[NN * EMB];       // preactivation ping
__device__ float g_P1[NN * EMB];       // preactivation pong
__device__ float g_v[EMB + 1];         // collapsed head vector + scalar

// ---------------- f32x2 packed-FMA helpers (Blackwell FFMA2) ----------------
#define DUP_F32X2(d, f) \
    asm("mov.b64 %0, {%1, %1};" : "=l"(d) : "r"(__float_as_uint(f)))
#define FMA_F32X2(acc, a, b) \
    asm("fma.rn.f32x2 %0, %1, %2, %0;" : "+l"(acc) : "l"(a), "l"(b))
#define UNPK_F32X2(lo, hi, p) \
    asm("mov.b64 {%0, %1}, %2;" : "=f"(lo), "=f"(hi) : "l"(p))

// ---------------- kernels ----------------

// h = relu(edge_attr @ w1 + b1), with trailing 1.0 channel. Two weight sets at once.
__global__ void edge_mlp_kernel(const float* __restrict__ ea,
                                const float* __restrict__ w1a, const float* __restrict__ b1a,
                                const float* __restrict__ w1b, const float* __restrict__ b1b) {
    __shared__ float swa[FE * 16], swb[FE * 16], sba[16], sbb[16];
    int tid = threadIdx.x;
    for (int t = tid; t < FE * 16; t += blockDim.x) { swa[t] = w1a[t]; swb[t] = w1b[t]; }
    if (tid < 16) { sba[tid] = b1a[tid]; sbb[tid] = b1b[tid]; }
    __syncthreads();
    int e = blockIdx.x * blockDim.x + tid;
    if (e >= EE) return;
    float a[FE];
#pragma unroll
    for (int i = 0; i < FE; i++) a[i] = ea[e * FE + i];
#pragma unroll
    for (int j = 0; j < 16; j++) {
        float s = sba[j], s2 = sbb[j];
#pragma unroll
        for (int i = 0; i < FE; i++) { s += a[i] * swa[i * 16 + j]; s2 += a[i] * swb[i * 16 + j]; }
        g_h0[e * HC + j] = fmaxf(s, 0.f);
        g_h1[e * HC + j] = fmaxf(s2, 0.f);
    }
    g_h0[e * HC + 16] = 1.f;
    g_h1[e * HC + 16] = 1.f;
}

// Build the three extended weight matrices in one launch.
__global__ void build_weights_kernel(const float* __restrict__ w2_0, const float* __restrict__ b2_0,
                                     const float* __restrict__ root0,
                                     const float* __restrict__ w2_1, const float* __restrict__ b2_1,
                                     const float* __restrict__ root1, const float* __restrict__ root2) {
    int idx = blockIdx.x * blockDim.x + threadIdx.x;
    if (idx < EMB * NB) {
        int i = idx / NB, r = idx - i * NB;
        if (r < ZC) {
            int k = r >> 6, o = r & 63;
            float vz = (k < 16) ? w2_1[k * (EMB * EMB) + i * EMB + o] : b2_1[i * EMB + o];
            g_Wr1a[idx] = vz; g_Wr1b[idx] = vz;
        } else {
            int o = r - ZC;
            g_Wr1a[idx] = root1[i * EMB + o];
            g_Wr1b[idx] = root2[i * EMB + o];
        }
    }
    if (idx < FIN * NB) {
        int i = idx / NB, r = idx - i * NB;
        if (r < ZC) {
            int k = r >> 6, o = r & 63;
            g_Wr0[idx] = (k < 16) ? w2_0[k * (FIN * EMB) + i * EMB + o] : b2_0[i * EMB + o];
        } else {
            g_Wr0[idx] = root0[i * EMB + (r - ZC)];
        }
    }
}

// C[M x 1152] = act(A[M x K]) @ B[K x 1152].
// Cols [0,1088) -> z buffer.  Cols [1088,1152) -> agg init (val + bias).
// 128x64 tile, 256 threads, 8x4 microtile. Inner product uses FFMA2 (f32x2):
// accumulators paired over m so a-pairs load directly as 64-bit from m-major As.
#define BM 128
#define BN 64
#define BK 32
__global__ __launch_bounds__(256) void gemm_kernel(const float* __restrict__ A,
                                                   const float* __restrict__ B,
                                                   float* __restrict__ z,
                                                   float* __restrict__ agg,
                                                   const float* __restrict__ bias,
                                                   int M, int K, int relu_a) {
    __shared__ float As[BK][BM + 4];   // row stride 132 floats = 528B (16B aligned)
    __shared__ float Bs[BK][BN + 4];
    int tid = threadIdx.x;
    int tx = tid & 15, ty = tid >> 4;
    int m0 = blockIdx.y * BM;
    int n0 = blockIdx.x * BN;
    unsigned long long acc2[4][4] = {};   // [m-pair][n], each = packed (f_even, f_odd)

    for (int kb = 0; kb < K; kb += BK) {
        if ((K & 3) == 0) {
            for (int t = tid; t < BM * (BK / 4); t += 256) {
                int m = t >> 3;
                int k4 = (t & 7) << 2;
                int gm = m0 + m, gk = kb + k4;
                float4 v = make_float4(0.f, 0.f, 0.f, 0.f);
                if (gm < M && gk < K) v = *(const float4*)&A[(size_t)gm * K + gk];
                if (relu_a) {
                    v.x = fmaxf(v.x, 0.f); v.y = fmaxf(v.y, 0.f);
                    v.z = fmaxf(v.z, 0.f); v.w = fmaxf(v.w, 0.f);
                }
                As[k4][m] = v.x; As[k4 + 1][m] = v.y; As[k4 + 2][m] = v.z; As[k4 + 3][m] = v.w;
            }
        } else {
            for (int t = tid; t < BM * BK; t += 256) {
                int m = t >> 5, k = t & (BK - 1);
                int gm = m0 + m, gk = kb + k;
                float v = (gm < M && gk < K) ? A[(size_t)gm * K + gk] : 0.f;
                if (relu_a) v = fmaxf(v, 0.f);
                As[k][m] = v;
            }
        }
        for (int t = tid; t < BK * (BN / 4); t += 256) {
            int k = t >> 4;
            int n4 = (t & 15) << 2;
            int gk = kb + k;
            float4 v = make_float4(0.f, 0.f, 0.f, 0.f);
            if (gk < K) v = *(const float4*)&B[(size_t)gk * NB + n0 + n4];
            *(float4*)&Bs[k][n4] = v;
        }
        __syncthreads();
#pragma unroll
        for (int k = 0; k < BK; k++) {
            // a: 8 m-values as 4 packed pairs, loaded directly as 64-bit lanes
            ulonglong2 av0 = *(const ulonglong2*)&As[k][ty * 8];
            ulonglong2 av1 = *(const ulonglong2*)&As[k][ty * 8 + 4];
            float4 b = *(const float4*)&Bs[k][tx * 4];
            unsigned long long ap[4] = {av0.x, av0.y, av1.x, av1.y};
            unsigned long long bd[4];
            DUP_F32X2(bd[0], b.x); DUP_F32X2(bd[1], b.y);
            DUP_F32X2(bd[2], b.z); DUP_F32X2(bd[3], b.w);
#pragma unroll
            for (int i = 0; i < 4; i++)
#pragma unroll
                for (int j = 0; j < 4; j++) FMA_F32X2(acc2[i][j], ap[i], bd[j]);
        }
        __syncthreads();
    }

    // unpack + store
    if (n0 < ZC) {
#pragma unroll
        for (int i = 0; i < 4; i++) {
            int gm = m0 + ty * 8 + 2 * i;
            float lo[4], hi[4];
#pragma unroll
            for (int j = 0; j < 4; j++) UNPK_F32X2(lo[j], hi[j], acc2[i][j]);
            if (gm < M)
                *(float4*)&z[(size_t)gm * ZC + n0 + tx * 4] = make_float4(lo[0], lo[1], lo[2], lo[3]);
            if (gm + 1 < M)
                *(float4*)&z[(size_t)(gm + 1) * ZC + n0 + tx * 4] = make_float4(hi[0], hi[1], hi[2], hi[3]);
        }
    } else {
        float4 bb = *(const float4*)&bias[tx * 4];
#pragma unroll
        for (int i = 0; i < 4; i++) {
            int gm = m0 + ty * 8 + 2 * i;
            float lo[4], hi[4];
#pragma unroll
            for (int j = 0; j < 4; j++) UNPK_F32X2(lo[j], hi[j], acc2[i][j]);
            if (gm < M)
                *(float4*)&agg[(size_t)gm * EMB + tx * 4] =
                    make_float4(lo[0] + bb.x, lo[1] + bb.y, lo[2] + bb.z, lo[3] + bb.w);
            if (gm + 1 < M)
                *(float4*)&agg[(size_t)(gm + 1) * EMB + tx * 4] =
                    make_float4(hi[0] + bb.x, hi[1] + bb.y, hi[2] + bb.z, hi[3] + bb.w);
        }
    }
}

// Per edge (one warp): msg[o] = sum_k h'[k] * z[src][k*64+o]; atomicAdd into agg[dst].
// Vectorized: each lane reads float4 (4 o-columns), warp covers 2 k-rows per pass.
// Lane l handles o = (l&15)*4 .. +3 for k-parity (l>=16); halves combined via shfl_xor(16).
__global__ __launch_bounds__(256) void edge_agg_kernel(const int* __restrict__ ei,
                                                       const float* __restrict__ h,
                                                       const float* __restrict__ z,
                                                       float* __restrict__ agg) {
    int e = blockIdx.x * 8 + (threadIdx.x >> 5);
    if (e >= EE) return;
    int lane = threadIdx.x & 31;
    int src = ei[e];
    int dst = ei[EE + e];
    const float4* zr = (const float4*)(z + (size_t)src * ZC);
    float hv = (lane < HC) ? h[e * HC + lane] : 0.f;
    int khalf = lane >> 4;               // 0: even k rows, 1: odd k rows
    float a0 = 0.f, a1 = 0.f, a2 = 0.f, a3 = 0.f;
#pragma unroll
    for (int j = 0; j < 9; j++) {
        float hk = __shfl_sync(0xFFFFFFFFu, hv, 2 * j + khalf);   // k = 2j+khalf (<=17; lane17 hv=0)
        if (j < 8 || khalf == 0) {       // float4 idx j*32+lane < 272 (17 k-rows)
            float4 v = zr[j * 32 + lane];
            a0 += hk * v.x; a1 += hk * v.y; a2 += hk * v.z; a3 += hk * v.w;
        }
    }
    a0 += __shfl_xor_sync(0xFFFFFFFFu, a0, 16);
    a1 += __shfl_xor_sync(0xFFFFFFFFu, a1, 16);
    a2 += __shfl_xor_sync(0xFFFFFFFFu, a2, 16);
    a3 += __shfl_xor_sync(0xFFFFFFFFu, a3, 16);
    if (lane < 16) {
        float* ap = agg + (size_t)dst * EMB + lane * 4;
        atomicAdd(ap + 0, a0);
        atomicAdd(ap + 1, a1);
        atomicAdd(ap + 2, a2);
        atomicAdd(ap + 3, a3);
    }
}

// v = lin0_w @ lin1_w ; c = lin0_b . lin1_w + lin1_b
__global__ void head_v_kernel(const float* __restrict__ l0w, const float* __restrict__ l0b,
                              const float* __restrict__ l1w, const float* __restrict__ l1b) {
    int i = threadIdx.x;
    float s = 0.f;
    for (int j = 0; j < EMB; j++) s += l0w[i * EMB + j] * l1w[j];
    g_v[i] = s;
    if (i == 0) {
        float c = l1b[0];
        for (int j = 0; j < EMB; j++) c += l0b[j] * l1w[j];
        g_v[EMB] = c;
    }
}

// Fused: segment_max(relu(h)) over sorted batch, dot with head vector.
__global__ __launch_bounds__(256) void pool_head_kernel(const float* __restrict__ h,
                                                        const int* __restrict__ batch,
                                                        float* __restrict__ out) {
    int b = blockIdx.x, t = threadIdx.x;
    __shared__ int sb[2];
    __shared__ float sred[256];
    if (t < 2) {
        int target = b + t, lo = 0, hi = NN;
        while (lo < hi) { int mid = (lo + hi) >> 1; if (batch[mid] < target) lo = mid + 1; else hi = mid; }
        sb[t] = lo;
    }
    __syncthreads();
    int o = t & 63, c = t >> 6;
    float m = -FLT_MAX;
    for (int n = sb[0] + c; n < sb[1]; n += 4) m = fmaxf(m, h[(size_t)n * EMB + o]);
    sred[t] = m;
    __syncthreads();
    if (t < 64) {
        float mm = fmaxf(fmaxf(sred[t], sred[t + 64]), fmaxf(sred[t + 128], sred[t + 192]));
        mm = fmaxf(mm, 0.f);   // relu commutes with max; segments are nonempty
        sred[t] = mm * g_v[t];
    }
    __syncthreads();
    for (int s = 32; s > 0; s >>= 1) {
        if (t < s) sred[t] += sred[t + s];
        __syncthreads();
    }
    if (t == 0) out[b] = sred[0] + g_v[EMB];
}

// ---------------- launch ----------------
extern "C" void kernel_launch(void* const* d_in, const int* in_sizes, int n_in,
                              void* d_out, int out_size) {
    const float* x     = (const float*)d_in[0];
    const float* ea    = (const float*)d_in[1];
    const int*   ei    = (const int*)d_in[2];
    const int*   batch = (const int*)d_in[3];
    const float* ew0_1 = (const float*)d_in[4];
    const float* eb0_1 = (const float*)d_in[5];
    const float* ew0_2 = (const float*)d_in[6];
    const float* eb0_2 = (const float*)d_in[7];
    const float* ew1_1 = (const float*)d_in[8];
    const float* eb1_1 = (const float*)d_in[9];
    const float* ew1_2 = (const float*)d_in[10];
    const float* eb1_2 = (const float*)d_in[11];
    const float* root0 = (const float*)d_in[12];
    const float* bias0 = (const float*)d_in[13];
    const float* root1 = (const float*)d_in[14];
    const float* bias1 = (const float*)d_in[15];
    const float* root2 = (const float*)d_in[16];
    const float* bias2 = (const float*)d_in[17];
    const float* l0w   = (const float*)d_in[18];
    const float* l0b   = (const float*)d_in[19];
    const float* l1w   = (const float*)d_in[20];
    const float* l1b   = (const float*)d_in[21];
    float* out = (float*)d_out;

    float *h0p, *h1p, *Wr0p, *Wr1ap, *Wr1bp, *zp, *P0p, *P1p;
    cudaGetSymbolAddress((void**)&h0p,   g_h0);
    cudaGetSymbolAddress((void**)&h1p,   g_h1);
    cudaGetSymbolAddress((void**)&Wr0p,  g_Wr0);
    cudaGetSymbolAddress((void**)&Wr1ap, g_Wr1a);
    cudaGetSymbolAddress((void**)&Wr1bp, g_Wr1b);
    cudaGetSymbolAddress((void**)&zp,    g_z);
    cudaGetSymbolAddress((void**)&P0p,   g_P0);
    cudaGetSymbolAddress((void**)&P1p,   g_P1);

    dim3 gemm_grid(NB / BN, (NN + BM - 1) / BM);   // 18 x 79

    edge_mlp_kernel<<<(EE + 255) / 256, 256>>>(ea, ew0_1, eb0_1, ew1_1, eb1_1);
    build_weights_kernel<<<(EMB * NB + 255) / 256, 256>>>(ew0_2, eb0_2, root0,
                                                          ew1_2, eb1_2, root1, root2);

    // layer 0: P0 = x@root0 + bias0 (gemm epilogue) + scatter(h0, z)
    gemm_kernel<<<gemm_grid, 256>>>(x, Wr0p, zp, P0p, bias0, NN, FIN, 0);
    edge_agg_kernel<<<(EE + 7) / 8, 256>>>(ei, h0p, zp, P0p);

    // layer 1: A = relu(P0)
    gemm_kernel<<<gemm_grid, 256>>>(P0p, Wr1ap, zp, P1p, bias1, NN, EMB, 1);
    edge_agg_kernel<<<(EE + 7) / 8, 256>>>(ei, h1p, zp, P1p);

    // layer 2: A = relu(P1), agg init back into P0
    gemm_kernel<<<gemm_grid, 256>>>(P1p, Wr1bp, zp, P0p, bias2, NN, EMB, 1);
    edge_agg_kernel<<<(EE + 7) / 8, 256>>>(ei, h1p, zp, P0p);

    // head
    head_v_kernel<<<1, EMB>>>(l0w, l0b, l1w, l1b);
    pool_head_kernel<<<BB, 256>>>(P0p, batch, out);
}

// round 8
// speedup vs baseline: 1.4550x; 1.0016x over previous
#include <cuda_runtime.h>
#include <cfloat>

#define NN 10000
#define EE 40000
#define FIN 30
#define FE 11
#define EMB 64
#define BB 128
#define HC 17            // 16 hidden channels + 1 folded-bias channel
#define ZC (HC * EMB)    // 1088
#define NB (ZC + EMB)    // 1152 = B matrix width (z cols + root cols)

// ---------------- device scratch (static globals — no allocation) ----------------
__device__ float g_h0[EE * HC];        // layer-0 edge MLP output (+1 channel)
__device__ float g_h1[EE * HC];        // layer-1/2 edge MLP output (shared weights)
__device__ float g_Wr0[FIN * NB];      // [Wr | root0] for layer 0
__device__ float g_Wr1a[EMB * NB];     // [Wr1 | root1]
__device__ float g_Wr1b[EMB * NB];     // [Wr1 | root2]
__device__ float g_z[NN * ZC];         // per-node factorized tensor [N, 17*64]
__device__ float g_P0[NN * EMB];       // preactivation ping
__device__ float g_P1[NN * EMB];       // preactivation pong
__device__ float g_v[EMB + 1];         // collapsed head vector + scalar

// ---------------- f32x2 packed-FMA helpers (Blackwell FFMA2) ----------------
#define DUP_F32X2(d, f) \
    asm("mov.b64 %0, {%1, %1};" : "=l"(d) : "r"(__float_as_uint(f)))
#define FMA_F32X2(acc, a, b) \
    asm("fma.rn.f32x2 %0, %1, %2, %0;" : "+l"(acc) : "l"(a), "l"(b))
#define UNPK_F32X2(lo, hi, p) \
    asm("mov.b64 {%0, %1}, %2;" : "=f"(lo), "=f"(hi) : "l"(p))

// ---------------- kernels ----------------

// h = relu(edge_attr @ w1 + b1), with trailing 1.0 channel. Two weight sets at once.
__global__ void edge_mlp_kernel(const float* __restrict__ ea,
                                const float* __restrict__ w1a, const float* __restrict__ b1a,
                                const float* __restrict__ w1b, const float* __restrict__ b1b) {
    __shared__ float swa[FE * 16], swb[FE * 16], sba[16], sbb[16];
    int tid = threadIdx.x;
    for (int t = tid; t < FE * 16; t += blockDim.x) { swa[t] = w1a[t]; swb[t] = w1b[t]; }
    if (tid < 16) { sba[tid] = b1a[tid]; sbb[tid] = b1b[tid]; }
    __syncthreads();
    int e = blockIdx.x * blockDim.x + tid;
    if (e >= EE) return;
    float a[FE];
#pragma unroll
    for (int i = 0; i < FE; i++) a[i] = ea[e * FE + i];
#pragma unroll
    for (int j = 0; j < 16; j++) {
        float s = sba[j], s2 = sbb[j];
#pragma unroll
        for (int i = 0; i < FE; i++) { s += a[i] * swa[i * 16 + j]; s2 += a[i] * swb[i * 16 + j]; }
        g_h0[e * HC + j] = fmaxf(s, 0.f);
        g_h1[e * HC + j] = fmaxf(s2, 0.f);
    }
    g_h0[e * HC + 16] = 1.f;
    g_h1[e * HC + 16] = 1.f;
}

// Build the three extended weight matrices in one launch.
__global__ void build_weights_kernel(const float* __restrict__ w2_0, const float* __restrict__ b2_0,
                                     const float* __restrict__ root0,
                                     const float* __restrict__ w2_1, const float* __restrict__ b2_1,
                                     const float* __restrict__ root1, const float* __restrict__ root2) {
    int idx = blockIdx.x * blockDim.x + threadIdx.x;
    if (idx < EMB * NB) {
        int i = idx / NB, r = idx - i * NB;
        if (r < ZC) {
            int k = r >> 6, o = r & 63;
            float vz = (k < 16) ? w2_1[k * (EMB * EMB) + i * EMB + o] : b2_1[i * EMB + o];
            g_Wr1a[idx] = vz; g_Wr1b[idx] = vz;
        } else {
            int o = r - ZC;
            g_Wr1a[idx] = root1[i * EMB + o];
            g_Wr1b[idx] = root2[i * EMB + o];
        }
    }
    if (idx < FIN * NB) {
        int i = idx / NB, r = idx - i * NB;
        if (r < ZC) {
            int k = r >> 6, o = r & 63;
            g_Wr0[idx] = (k < 16) ? w2_0[k * (FIN * EMB) + i * EMB + o] : b2_0[i * EMB + o];
        } else {
            g_Wr0[idx] = root0[i * EMB + (r - ZC)];
        }
    }
}

// C[M x 1152] = act(A[M x K]) @ B[K x 1152].
// Cols [0,1088) -> z buffer.  Cols [1088,1152) -> agg init (val + bias).
// 128x64 tile, 256 threads, 8x4 microtile. Inner product uses FFMA2 (f32x2):
// accumulators paired over m so a-pairs load directly as 64-bit from m-major As.
#define BM 128
#define BN 64
#define BK 32
__global__ __launch_bounds__(256) void gemm_kernel(const float* __restrict__ A,
                                                   const float* __restrict__ B,
                                                   float* __restrict__ z,
                                                   float* __restrict__ agg,
                                                   const float* __restrict__ bias,
                                                   int M, int K, int relu_a) {
    __shared__ float As[BK][BM + 4];   // row stride 132 floats = 528B (16B aligned)
    __shared__ float Bs[BK][BN + 4];
    int tid = threadIdx.x;
    int tx = tid & 15, ty = tid >> 4;
    int m0 = blockIdx.y * BM;
    int n0 = blockIdx.x * BN;
    unsigned long long acc2[4][4] = {};   // [m-pair][n], each = packed (f_even, f_odd)

    for (int kb = 0; kb < K; kb += BK) {
        if ((K & 3) == 0) {
            for (int t = tid; t < BM * (BK / 4); t += 256) {
                int m = t >> 3;
                int k4 = (t & 7) << 2;
                int gm = m0 + m, gk = kb + k4;
                float4 v = make_float4(0.f, 0.f, 0.f, 0.f);
                if (gm < M && gk < K) v = *(const float4*)&A[(size_t)gm * K + gk];
                if (relu_a) {
                    v.x = fmaxf(v.x, 0.f); v.y = fmaxf(v.y, 0.f);
                    v.z = fmaxf(v.z, 0.f); v.w = fmaxf(v.w, 0.f);
                }
                As[k4][m] = v.x; As[k4 + 1][m] = v.y; As[k4 + 2][m] = v.z; As[k4 + 3][m] = v.w;
            }
        } else {
            for (int t = tid; t < BM * BK; t += 256) {
                int m = t >> 5, k = t & (BK - 1);
                int gm = m0 + m, gk = kb + k;
                float v = (gm < M && gk < K) ? A[(size_t)gm * K + gk] : 0.f;
                if (relu_a) v = fmaxf(v, 0.f);
                As[k][m] = v;
            }
        }
        for (int t = tid; t < BK * (BN / 4); t += 256) {
            int k = t >> 4;
            int n4 = (t & 15) << 2;
            int gk = kb + k;
            float4 v = make_float4(0.f, 0.f, 0.f, 0.f);
            if (gk < K) v = *(const float4*)&B[(size_t)gk * NB + n0 + n4];
            *(float4*)&Bs[k][n4] = v;
        }
        __syncthreads();
#pragma unroll
        for (int k = 0; k < BK; k++) {
            // a: 8 m-values as 4 packed pairs, loaded directly as 64-bit lanes
            ulonglong2 av0 = *(const ulonglong2*)&As[k][ty * 8];
            ulonglong2 av1 = *(const ulonglong2*)&As[k][ty * 8 + 4];
            float4 b = *(const float4*)&Bs[k][tx * 4];
            unsigned long long ap[4] = {av0.x, av0.y, av1.x, av1.y};
            unsigned long long bd[4];
            DUP_F32X2(bd[0], b.x); DUP_F32X2(bd[1], b.y);
            DUP_F32X2(bd[2], b.z); DUP_F32X2(bd[3], b.w);
#pragma unroll
            for (int i = 0; i < 4; i++)
#pragma unroll
                for (int j = 0; j < 4; j++) FMA_F32X2(acc2[i][j], ap[i], bd[j]);
        }
        __syncthreads();
    }

    // unpack + store
    if (n0 < ZC) {
#pragma unroll
        for (int i = 0; i < 4; i++) {
            int gm = m0 + ty * 8 + 2 * i;
            float lo[4], hi[4];
#pragma unroll
            for (int j = 0; j < 4; j++) UNPK_F32X2(lo[j], hi[j], acc2[i][j]);
            if (gm < M)
                *(float4*)&z[(size_t)gm * ZC + n0 + tx * 4] = make_float4(lo[0], lo[1], lo[2], lo[3]);
            if (gm + 1 < M)
                *(float4*)&z[(size_t)(gm + 1) * ZC + n0 + tx * 4] = make_float4(hi[0], hi[1], hi[2], hi[3]);
        }
    } else {
        float4 bb = *(const float4*)&bias[tx * 4];
#pragma unroll
        for (int i = 0; i < 4; i++) {
            int gm = m0 + ty * 8 + 2 * i;
            float lo[4], hi[4];
#pragma unroll
            for (int j = 0; j < 4; j++) UNPK_F32X2(lo[j], hi[j], acc2[i][j]);
            if (gm < M)
                *(float4*)&agg[(size_t)gm * EMB + tx * 4] =
                    make_float4(lo[0] + bb.x, lo[1] + bb.y, lo[2] + bb.z, lo[3] + bb.w);
            if (gm + 1 < M)
                *(float4*)&agg[(size_t)(gm + 1) * EMB + tx * 4] =
                    make_float4(hi[0] + bb.x, hi[1] + bb.y, hi[2] + bb.z, hi[3] + bb.w);
        }
    }
}

// Per edge (one warp): msg[o] = sum_k h'[k] * z[src][k*64+o]; atomicAdd into agg[dst].
// Vectorized: each lane reads float4 (4 o-columns), warp covers 2 k-rows per pass.
// Lane l handles o = (l&15)*4 .. +3 for k-parity (l>=16); halves combined via shfl_xor(16).
__global__ __launch_bounds__(256) void edge_agg_kernel(const int* __restrict__ ei,
                                                       const float* __restrict__ h,
                                                       const float* __restrict__ z,
                                                       float* __restrict__ agg) {
    int e = blockIdx.x * 8 + (threadIdx.x >> 5);
    if (e >= EE) return;
    int lane = threadIdx.x & 31;
    int src = ei[e];
    int dst = ei[EE + e];
    const float4* zr = (const float4*)(z + (size_t)src * ZC);
    float hv = (lane < HC) ? h[e * HC + lane] : 0.f;
    int khalf = lane >> 4;               // 0: even k rows, 1: odd k rows
    float a0 = 0.f, a1 = 0.f, a2 = 0.f, a3 = 0.f;
#pragma unroll
    for (int j = 0; j < 9; j++) {
        float hk = __shfl_sync(0xFFFFFFFFu, hv, 2 * j + khalf);   // k = 2j+khalf (<=17; lane17 hv=0)
        if (j < 8 || khalf == 0) {       // float4 idx j*32+lane < 272 (17 k-rows)
            float4 v = zr[j * 32 + lane];
            a0 += hk * v.x; a1 += hk * v.y; a2 += hk * v.z; a3 += hk * v.w;
        }
    }
    a0 += __shfl_xor_sync(0xFFFFFFFFu, a0, 16);
    a1 += __shfl_xor_sync(0xFFFFFFFFu, a1, 16);
    a2 += __shfl_xor_sync(0xFFFFFFFFu, a2, 16);
    a3 += __shfl_xor_sync(0xFFFFFFFFu, a3, 16);
    if (lane < 16) {
        float* ap = agg + (size_t)dst * EMB + lane * 4;
        atomicAdd(ap + 0, a0);
        atomicAdd(ap + 1, a1);
        atomicAdd(ap + 2, a2);
        atomicAdd(ap + 3, a3);
    }
}

// v = lin0_w @ lin1_w ; c = lin0_b . lin1_w + lin1_b
__global__ void head_v_kernel(const float* __restrict__ l0w, const float* __restrict__ l0b,
                              const float* __restrict__ l1w, const float* __restrict__ l1b) {
    int i = threadIdx.x;
    float s = 0.f;
    for (int j = 0; j < EMB; j++) s += l0w[i * EMB + j] * l1w[j];
    g_v[i] = s;
    if (i == 0) {
        float c = l1b[0];
        for (int j = 0; j < EMB; j++) c += l0b[j] * l1w[j];
        g_v[EMB] = c;
    }
}

// Fused: segment_max(relu(h)) over sorted batch, dot with head vector.
__global__ __launch_bounds__(256) void pool_head_kernel(const float* __restrict__ h,
                                                        const int* __restrict__ batch,
                                                        float* __restrict__ out) {
    int b = blockIdx.x, t = threadIdx.x;
    __shared__ int sb[2];
    __shared__ float sred[256];
    if (t < 2) {
        int target = b + t, lo = 0, hi = NN;
        while (lo < hi) { int mid = (lo + hi) >> 1; if (batch[mid] < target) lo = mid + 1; else hi = mid; }
        sb[t] = lo;
    }
    __syncthreads();
    int o = t & 63, c = t >> 6;
    float m = -FLT_MAX;
    for (int n = sb[0] + c; n < sb[1]; n += 4) m = fmaxf(m, h[(size_t)n * EMB + o]);
    sred[t] = m;
    __syncthreads();
    if (t < 64) {
        float mm = fmaxf(fmaxf(sred[t], sred[t + 64]), fmaxf(sred[t + 128], sred[t + 192]));
        mm = fmaxf(mm, 0.f);   // relu commutes with max; segments are nonempty
        sred[t] = mm * g_v[t];
    }
    __syncthreads();
    for (int s = 32; s > 0; s >>= 1) {
        if (t < s) sred[t] += sred[t + s];
        __syncthreads();
    }
    if (t == 0) out[b] = sred[0] + g_v[EMB];
}

// ---------------- launch ----------------
extern "C" void kernel_launch(void* const* d_in, const int* in_sizes, int n_in,
                              void* d_out, int out_size) {
    const float* x     = (const float*)d_in[0];
    const float* ea    = (const float*)d_in[1];
    const int*   ei    = (const int*)d_in[2];
    const int*   batch = (const int*)d_in[3];
    const float* ew0_1 = (const float*)d_in[4];
    const float* eb0_1 = (const float*)d_in[5];
    const float* ew0_2 = (const float*)d_in[6];
    const float* eb0_2 = (const float*)d_in[7];
    const float* ew1_1 = (const float*)d_in[8];
    const float* eb1_1 = (const float*)d_in[9];
    const float* ew1_2 = (const float*)d_in[10];
    const float* eb1_2 = (const float*)d_in[11];
    const float* root0 = (const float*)d_in[12];
    const float* bias0 = (const float*)d_in[13];
    const float* root1 = (const float*)d_in[14];
    const float* bias1 = (const float*)d_in[15];
    const float* root2 = (const float*)d_in[16];
    const float* bias2 = (const float*)d_in[17];
    const float* l0w   = (const float*)d_in[18];
    const float* l0b   = (const float*)d_in[19];
    const float* l1w   = (const float*)d_in[20];
    const float* l1b   = (const float*)d_in[21];
    float* out = (float*)d_out;

    float *h0p, *h1p, *Wr0p, *Wr1ap, *Wr1bp, *zp, *P0p, *P1p;
    cudaGetSymbolAddress((void**)&h0p,   g_h0);
    cudaGetSymbolAddress((void**)&h1p,   g_h1);
    cudaGetSymbolAddress((void**)&Wr0p,  g_Wr0);
    cudaGetSymbolAddress((void**)&Wr1ap, g_Wr1a);
    cudaGetSymbolAddress((void**)&Wr1bp, g_Wr1b);
    cudaGetSymbolAddress((void**)&zp,    g_z);
    cudaGetSymbolAddress((void**)&P0p,   g_P0);
    cudaGetSymbolAddress((void**)&P1p,   g_P1);

    dim3 gemm_grid(NB / BN, (NN + BM - 1) / BM);   // 18 x 79

    edge_mlp_kernel<<<(EE + 255) / 256, 256>>>(ea, ew0_1, eb0_1, ew1_1, eb1_1);
    build_weights_kernel<<<(EMB * NB + 255) / 256, 256>>>(ew0_2, eb0_2, root0,
                                                          ew1_2, eb1_2, root1, root2);

    // layer 0: P0 = x@root0 + bias0 (gemm epilogue) + scatter(h0, z)
    gemm_kernel<<<gemm_grid, 256>>>(x, Wr0p, zp, P0p, bias0, NN, FIN, 0);
    edge_agg_kernel<<<(EE + 7) / 8, 256>>>(ei, h0p, zp, P0p);

    // layer 1: A = relu(P0)
    gemm_kernel<<<gemm_grid, 256>>>(P0p, Wr1ap, zp, P1p, bias1, NN, EMB, 1);
    edge_agg_kernel<<<(EE + 7) / 8, 256>>>(ei, h1p, zp, P1p);

    // layer 2: A = relu(P1), agg init back into P0
    gemm_kernel<<<gemm_grid, 256>>>(P1p, Wr1bp, zp, P0p, bias2, NN, EMB, 1);
    edge_agg_kernel<<<(EE + 7) / 8, 256>>>(ei, h1p, zp, P0p);

    // head
    head_v_kernel<<<1, EMB>>>(l0w, l0b, l1w, l1b);
    pool_head_kernel<<<BB, 256>>>(P0p, batch, out);
}